// round 2
// baseline (speedup 1.0000x reference)
#include <cuda_runtime.h>
#include <cuda_bf16.h>
#include <math.h>

// MatrixMLP: per-sample 4x4 pinv solve + 24->128->64->4 MLP, B = 524288.
// R2: fp32 cofactor fast path + fp64 Jacobi-SVD pinv slow path (emulates
// jnp.linalg.pinv truncation, rcond = 40*2^-23) for near-singular samples.

#define NTHREADS 256

// JAX pinv rcond for float32, 4x4: 10 * max(M,N) * eps = 40 * 2^-23
#define RCOND2 2.2737367544323206e-11   // rcond^2

// Rare path: SVD-pinv via fp64 Jacobi eigendecomposition of A = H^T H.
// a: H row-major (H[r][c] = a[r*4+c]); y: rhs; xout: 4 outputs (unclipped).
__device__ __noinline__ void pinv_slow(const float* a, const float* yv, float* xout)
{
    double H[4][4], A[4][4], V[4][4];
    for (int r = 0; r < 4; r++)
        for (int c = 0; c < 4; c++)
            H[r][c] = (double)a[r * 4 + c];

    for (int i = 0; i < 4; i++)
        for (int j = 0; j < 4; j++) {
            double s = 0.0;
            for (int r = 0; r < 4; r++) s += H[r][i] * H[r][j];
            A[i][j] = s;
            V[i][j] = (i == j) ? 1.0 : 0.0;
        }

    // Cyclic Jacobi, 10 sweeps (overkill for 4x4 fp64 convergence)
    for (int sweep = 0; sweep < 10; sweep++) {
        for (int p = 0; p < 3; p++) {
            for (int q = p + 1; q < 4; q++) {
                double apq = A[p][q];
                if (fabs(apq) < 1e-300) continue;
                double app = A[p][p], aqq = A[q][q];
                double tau = (aqq - app) / (2.0 * apq);
                double t = ((tau >= 0.0) ? 1.0 : -1.0) /
                           (fabs(tau) + sqrt(1.0 + tau * tau));
                double c = 1.0 / sqrt(1.0 + t * t);
                double s = t * c;
                for (int k = 0; k < 4; k++) {
                    double akp = A[k][p], akq = A[k][q];
                    A[k][p] = c * akp - s * akq;
                    A[k][q] = s * akp + c * akq;
                }
                for (int k = 0; k < 4; k++) {
                    double apk = A[p][k], aqk = A[q][k];
                    A[p][k] = c * apk - s * aqk;
                    A[q][k] = s * apk + c * aqk;
                }
                for (int k = 0; k < 4; k++) {
                    double vkp = V[k][p], vkq = V[k][q];
                    V[k][p] = c * vkp - s * vkq;
                    V[k][q] = s * vkp + c * vkq;
                }
            }
        }
    }

    double lam[4];
    double lmax = 0.0;
    for (int i = 0; i < 4; i++) {
        lam[i] = A[i][i];
        if (lam[i] > lmax) lmax = lam[i];
    }
    const double thr = RCOND2 * lmax;   // keep iff sigma > rcond*sigma_max

    // z = H^T y
    double z[4];
    for (int i = 0; i < 4; i++) {
        double s = 0.0;
        for (int r = 0; r < 4; r++) s += H[r][i] * (double)yv[r];
        z[i] = s;
    }
    // w = V^T z, scaled by 1/lambda on kept modes
    double w[4];
    for (int i = 0; i < 4; i++) {
        double s = 0.0;
        for (int k = 0; k < 4; k++) s += V[k][i] * z[k];
        w[i] = (lam[i] > thr) ? (s / lam[i]) : 0.0;
    }
    for (int j = 0; j < 4; j++) {
        double s = 0.0;
        for (int i = 0; i < 4; i++) s += V[j][i] * w[i];
        xout[j] = (float)s;
    }
}

__global__ __launch_bounds__(NTHREADS)
void matrixmlp_kernel(const float* __restrict__ x,
                      const float* __restrict__ W1, const float* __restrict__ b1,
                      const float* __restrict__ W2, const float* __restrict__ b2,
                      const float* __restrict__ W3, const float* __restrict__ b3,
                      float* __restrict__ out)
{
    // ---- shared weights (46.9 KB) ----
    __shared__ __align__(16) float sW1[24 * 128];
    __shared__ __align__(16) float sW2[128 * 64];
    __shared__ __align__(16) float sW3[64 * 4];
    __shared__ __align__(16) float sb1[128];
    __shared__ __align__(16) float sb2[64];
    __shared__ __align__(16) float sb3[4];

    const int tid = threadIdx.x;
    {
        const float4* s;
        float4* d;
        s = (const float4*)W1; d = (float4*)sW1;
        for (int i = tid; i < 768; i += NTHREADS) d[i] = s[i];
        s = (const float4*)W2; d = (float4*)sW2;
        for (int i = tid; i < 2048; i += NTHREADS) d[i] = s[i];
        s = (const float4*)W3; d = (float4*)sW3;
        for (int i = tid; i < 64; i += NTHREADS) d[i] = s[i];
        s = (const float4*)b1; d = (float4*)sb1;
        for (int i = tid; i < 32; i += NTHREADS) d[i] = s[i];
        s = (const float4*)b2; d = (float4*)sb2;
        for (int i = tid; i < 16; i += NTHREADS) d[i] = s[i];
        if (tid == 0) ((float4*)sb3)[0] = ((const float4*)b3)[0];
    }
    __syncthreads();

    const int sample = blockIdx.x * NTHREADS + tid;

    // x sample = 20 floats = 5 float4 (80B stride keeps 16B alignment)
    const float4* xp = (const float4*)x + sample * 5;
    const float4 f0 = xp[0];
    const float4 f1 = xp[1];
    const float4 f2 = xp[2];
    const float4 f3 = xp[3];
    const float4 f4 = xp[4];

    // ---- 4x4 solve: H[r][c] = x[c][r]; solve H v = y, y[r] = x[4][r] ----
    const float a00 = f0.x, a01 = f1.x, a02 = f2.x, a03 = f3.x;
    const float a10 = f0.y, a11 = f1.y, a12 = f2.y, a13 = f3.y;
    const float a20 = f0.z, a21 = f1.z, a22 = f2.z, a23 = f3.z;
    const float a30 = f0.w, a31 = f1.w, a32 = f2.w, a33 = f3.w;

    const float s0 = a00 * a11 - a01 * a10;
    const float s1 = a00 * a12 - a02 * a10;
    const float s2 = a00 * a13 - a03 * a10;
    const float s3 = a01 * a12 - a02 * a11;
    const float s4 = a01 * a13 - a03 * a11;
    const float s5 = a02 * a13 - a03 * a12;
    const float c5 = a22 * a33 - a23 * a32;
    const float c4 = a21 * a33 - a23 * a31;
    const float c3 = a21 * a32 - a22 * a31;
    const float c2 = a20 * a33 - a23 * a30;
    const float c1 = a20 * a32 - a22 * a30;
    const float c0 = a20 * a31 - a21 * a30;

    const float det = s0 * c5 - s1 * c4 + s2 * c3 + s3 * c2 - s4 * c1 + s5 * c0;

    const float y0 = f4.x, y1 = f4.y, y2 = f4.z, y3 = f4.w;

    float v0, v1, v2, v3;

    // Frobenius^2 for scale-relative singularity test.
    const float F2 =
        a00*a00 + a01*a01 + a02*a02 + a03*a03 +
        a10*a10 + a11*a11 + a12*a12 + a13*a13 +
        a20*a20 + a21*a21 + a22*a22 + a23*a23 +
        a30*a30 + a31*a31 + a32*a32 + a33*a33;

    // |det| <= F^4 / kappa  =>  this catches ALL kappa > ~1e5 (where the
    // reference's fp32 SVD pinv may truncate / diverge from exact inverse).
    const bool well_cond = fabsf(det) > (3e-5f * F2 * F2 + 1e-5f);

    if (well_cond) {
        const float invdet = 1.0f / det;
        v0 = (( a11 * c5 - a12 * c4 + a13 * c3) * y0 +
              (-a01 * c5 + a02 * c4 - a03 * c3) * y1 +
              ( a31 * s5 - a32 * s4 + a33 * s3) * y2 +
              (-a21 * s5 + a22 * s4 - a23 * s3) * y3) * invdet;
        v1 = ((-a10 * c5 + a12 * c2 - a13 * c1) * y0 +
              ( a00 * c5 - a02 * c2 + a03 * c1) * y1 +
              (-a30 * s5 + a32 * s2 - a33 * s1) * y2 +
              ( a20 * s5 - a22 * s2 + a23 * s1) * y3) * invdet;
        v2 = (( a10 * c4 - a11 * c2 + a13 * c0) * y0 +
              (-a00 * c4 + a01 * c2 - a03 * c0) * y1 +
              ( a30 * s4 - a31 * s2 + a33 * s0) * y2 +
              (-a20 * s4 + a21 * s2 - a23 * s0) * y3) * invdet;
        v3 = ((-a10 * c3 + a11 * c1 - a12 * c0) * y0 +
              ( a00 * c3 - a01 * c1 + a02 * c0) * y1 +
              (-a30 * s3 + a31 * s1 - a32 * s0) * y2 +
              ( a20 * s3 - a21 * s1 + a22 * s0) * y3) * invdet;
    } else {
        float hm[16], yv[4], xo[4];
        hm[0]  = a00; hm[1]  = a01; hm[2]  = a02; hm[3]  = a03;
        hm[4]  = a10; hm[5]  = a11; hm[6]  = a12; hm[7]  = a13;
        hm[8]  = a20; hm[9]  = a21; hm[10] = a22; hm[11] = a23;
        hm[12] = a30; hm[13] = a31; hm[14] = a32; hm[15] = a33;
        yv[0] = y0; yv[1] = y1; yv[2] = y2; yv[3] = y3;
        pinv_slow(hm, yv, xo);
        v0 = xo[0]; v1 = xo[1]; v2 = xo[2]; v3 = xo[3];
    }

    // nan_to_num(nan=0, posinf=1, neginf=0) + clip(0,1) == __saturatef
    const float xls0 = __saturatef(v0);
    const float xls1 = __saturatef(v1);
    const float xls2 = __saturatef(v2);
    const float xls3 = __saturatef(v3);

    // ---- MLP input: [flat(20), x_ls(4)] ----
    float in[24];
    in[0]  = f0.x; in[1]  = f0.y; in[2]  = f0.z; in[3]  = f0.w;
    in[4]  = f1.x; in[5]  = f1.y; in[6]  = f1.z; in[7]  = f1.w;
    in[8]  = f2.x; in[9]  = f2.y; in[10] = f2.z; in[11] = f2.w;
    in[12] = f3.x; in[13] = f3.y; in[14] = f3.z; in[15] = f3.w;
    in[16] = f4.x; in[17] = f4.y; in[18] = f4.z; in[19] = f4.w;
    in[20] = xls0; in[21] = xls1; in[22] = xls2; in[23] = xls3;

    // ---- layer1 (24->128, relu) fused with layer2 accumulate (->64) ----
    float h2[64];
#pragma unroll
    for (int j = 0; j < 64; j++) h2[j] = sb2[j];

#pragma unroll 1
    for (int kc = 0; kc < 8; kc++) {
        float h1c[16];
        const int kbase = kc * 16;
#pragma unroll
        for (int t = 0; t < 16; t++) h1c[t] = sb1[kbase + t];

#pragma unroll
        for (int i = 0; i < 24; i++) {
            const float xi = in[i];
            const float4* wrow = (const float4*)(&sW1[i * 128 + kbase]);
#pragma unroll
            for (int q = 0; q < 4; q++) {
                const float4 w = wrow[q];
                h1c[q * 4 + 0] = fmaf(xi, w.x, h1c[q * 4 + 0]);
                h1c[q * 4 + 1] = fmaf(xi, w.y, h1c[q * 4 + 1]);
                h1c[q * 4 + 2] = fmaf(xi, w.z, h1c[q * 4 + 2]);
                h1c[q * 4 + 3] = fmaf(xi, w.w, h1c[q * 4 + 3]);
            }
        }

#pragma unroll
        for (int t = 0; t < 16; t++) {
            const float hv = fmaxf(h1c[t], 0.0f);
            const float4* w2row = (const float4*)(&sW2[(kbase + t) * 64]);
#pragma unroll
            for (int q = 0; q < 16; q++) {
                const float4 w = w2row[q];
                h2[q * 4 + 0] = fmaf(hv, w.x, h2[q * 4 + 0]);
                h2[q * 4 + 1] = fmaf(hv, w.y, h2[q * 4 + 1]);
                h2[q * 4 + 2] = fmaf(hv, w.z, h2[q * 4 + 2]);
                h2[q * 4 + 3] = fmaf(hv, w.w, h2[q * 4 + 3]);
            }
        }
    }

    // ---- layer3 (64->4) ----
    float d0 = sb3[0], d1 = sb3[1], d2 = sb3[2], d3 = sb3[3];
#pragma unroll
    for (int j = 0; j < 64; j++) {
        const float hv = fmaxf(h2[j], 0.0f);
        const float4 w = ((const float4*)sW3)[j];
        d0 = fmaf(hv, w.x, d0);
        d1 = fmaf(hv, w.y, d1);
        d2 = fmaf(hv, w.z, d2);
        d3 = fmaf(hv, w.w, d3);
    }

    float4 o;
    o.x = __saturatef(xls0 + d0);
    o.y = __saturatef(xls1 + d1);
    o.z = __saturatef(xls2 + d2);
    o.w = __saturatef(xls3 + d3);
    ((float4*)out)[sample] = o;
}

extern "C" void kernel_launch(void* const* d_in, const int* in_sizes, int n_in,
                              void* d_out, int out_size)
{
    const float* x  = (const float*)d_in[0];
    const float* W1 = (const float*)d_in[1];
    const float* b1 = (const float*)d_in[2];
    const float* W2 = (const float*)d_in[3];
    const float* b2 = (const float*)d_in[4];
    const float* W3 = (const float*)d_in[5];
    const float* b3 = (const float*)d_in[6];
    float* out = (float*)d_out;

    const int nsamples = in_sizes[0] / 20;  // 524288
    const int blocks = (nsamples + NTHREADS - 1) / NTHREADS;
    matrixmlp_kernel<<<blocks, NTHREADS>>>(x, W1, b1, W2, b2, W3, b3, out);
}

// round 4
// speedup vs baseline: 1.5975x; 1.5975x over previous
#include <cuda_runtime.h>
#include <cuda_bf16.h>
#include <math.h>
#include <stdint.h>

// MatrixMLP R4: scalar 4x4 pinv solve + MLP layers 1-2 on mma.sync tf32
// (m16n8k8 HMMA), layer 3 scalar fp32. Per-warp independent 32-sample tiles,
// fragment-packed weights in smem, persistent CTAs.

#define NTHREADS 128
#define TILE 128          // samples per CTA iteration (32 per warp)
#define NTILES_TOTAL 4096
#define RCOND2 2.2737367544323206e-11   // (40*2^-23)^2, JAX pinv fp32 4x4

// ---- smem layout (bytes from dynamic base) ----
#define O_W1F 0            // 3*16*64 u32 tf32 frag-packed  (12288 B)
#define O_W2F 12288        // 16*8*64 u32                   (32768 B)
#define O_B1P 45056        // 512 float2                    (4096 B)
#define O_B2P 49152        // 256 float2                    (2048 B)
#define O_W3P 51200        // 512 float4                    (8192 B)
#define O_B3  59392        // float4
#define O_XLS 59424        // 4 warps * 32 * float4         (2048 B)
#define O_H1  61472        // 4 warps * 32*40 u32           (20480 B)
#define SMEM_DYN 81952
#define H1_STRIDE 40       // floats per row (64-bit-store conflict-free)

__device__ __forceinline__ uint32_t f2tf(float f) {
    uint32_t r;
    asm("cvt.rna.tf32.f32 %0, %1;" : "=r"(r) : "f"(f));
    return r;
}

__device__ __forceinline__ void mma_tf32(float* c, const uint32_t* a,
                                         uint32_t b0, uint32_t b1) {
    asm volatile(
        "mma.sync.aligned.m16n8k8.row.col.f32.tf32.tf32.f32 "
        "{%0,%1,%2,%3}, {%4,%5,%6,%7}, {%8,%9}, {%0,%1,%2,%3};"
        : "+f"(c[0]), "+f"(c[1]), "+f"(c[2]), "+f"(c[3])
        : "r"(a[0]), "r"(a[1]), "r"(a[2]), "r"(a[3]), "r"(b0), "r"(b1));
}

// ---- rare-path fp64 Jacobi SVD pinv (matches jnp.linalg.pinv truncation) ----
__device__ __noinline__ void pinv_slow(const float* a, const float* yv, float* xout)
{
    double H[4][4], A[4][4], V[4][4];
    for (int r = 0; r < 4; r++)
        for (int c = 0; c < 4; c++) H[r][c] = (double)a[r * 4 + c];
    for (int i = 0; i < 4; i++)
        for (int j = 0; j < 4; j++) {
            double s = 0.0;
            for (int r = 0; r < 4; r++) s += H[r][i] * H[r][j];
            A[i][j] = s; V[i][j] = (i == j) ? 1.0 : 0.0;
        }
    for (int sweep = 0; sweep < 10; sweep++)
        for (int p = 0; p < 3; p++)
            for (int q = p + 1; q < 4; q++) {
                double apq = A[p][q];
                if (fabs(apq) < 1e-300) continue;
                double tau = (A[q][q] - A[p][p]) / (2.0 * apq);
                double t = ((tau >= 0.0) ? 1.0 : -1.0) /
                           (fabs(tau) + sqrt(1.0 + tau * tau));
                double c = 1.0 / sqrt(1.0 + t * t), s = t * c;
                for (int k = 0; k < 4; k++) {
                    double akp = A[k][p], akq = A[k][q];
                    A[k][p] = c * akp - s * akq; A[k][q] = s * akp + c * akq;
                }
                for (int k = 0; k < 4; k++) {
                    double apk = A[p][k], aqk = A[q][k];
                    A[p][k] = c * apk - s * aqk; A[q][k] = s * apk + c * aqk;
                }
                for (int k = 0; k < 4; k++) {
                    double vkp = V[k][p], vkq = V[k][q];
                    V[k][p] = c * vkp - s * vkq; V[k][q] = s * vkp + c * vkq;
                }
            }
    double lam[4], lmax = 0.0;
    for (int i = 0; i < 4; i++) { lam[i] = A[i][i]; if (lam[i] > lmax) lmax = lam[i]; }
    const double thr = RCOND2 * lmax;
    double z[4];
    for (int i = 0; i < 4; i++) {
        double s = 0.0;
        for (int r = 0; r < 4; r++) s += H[r][i] * (double)yv[r];
        z[i] = s;
    }
    double w[4];
    for (int i = 0; i < 4; i++) {
        double s = 0.0;
        for (int k = 0; k < 4; k++) s += V[k][i] * z[k];
        w[i] = (lam[i] > thr) ? (s / lam[i]) : 0.0;
    }
    for (int j = 0; j < 4; j++) {
        double s = 0.0;
        for (int i = 0; i < 4; i++) s += V[j][i] * w[i];
        xout[j] = (float)s;
    }
}

__global__ __launch_bounds__(NTHREADS)
void matrixmlp_hmma(const float* __restrict__ x,
                    const float* __restrict__ W1, const float* __restrict__ b1,
                    const float* __restrict__ W2, const float* __restrict__ b2,
                    const float* __restrict__ W3, const float* __restrict__ b3,
                    float* __restrict__ out, int ntiles)
{
    extern __shared__ char sm[];
    uint32_t* w1f = (uint32_t*)(sm + O_W1F);
    uint32_t* w2f = (uint32_t*)(sm + O_W2F);
    float2*   b1p = (float2*)(sm + O_B1P);
    float2*   b2p = (float2*)(sm + O_B2P);
    float4*   w3p = (float4*)(sm + O_W3P);
    float4*   b3s = (float4*)(sm + O_B3);

    const int tid  = threadIdx.x;
    const int lane = tid & 31;
    const int wid  = tid >> 5;
    const int q    = lane & 3;
    const int g    = lane >> 2;

    float*    xls = (float*)(sm + O_XLS + wid * 512);      // [32][4]
    uint32_t* h1  = (uint32_t*)(sm + O_H1 + wid * (32 * H1_STRIDE * 4));

    // ---- stage fragment-packed weights ----
    for (int i = tid; i < 3072; i += NTHREADS) {           // W1 frags
        int e = i & 1, ln = (i >> 1) & 31, fi = i >> 6;
        int kt = fi >> 4, nt = fi & 15;
        int kk = 8 * kt + (ln & 3) + 4 * e, nn = 8 * nt + (ln >> 2);
        w1f[(fi << 6) + ((ln << 1) | e)] = f2tf(W1[kk * 128 + nn]);
    }
    for (int i = tid; i < 8192; i += NTHREADS) {           // W2 frags
        int e = i & 1, ln = (i >> 1) & 31, fi = i >> 6;
        int kt = fi >> 3, nt = fi & 7;
        int kk = 8 * kt + (ln & 3) + 4 * e, nn = 8 * nt + (ln >> 2);
        w2f[(fi << 6) + ((ln << 1) | e)] = f2tf(W2[kk * 64 + nn]);
    }
    for (int i = tid; i < 512; i += NTHREADS) {            // b1 pairs
        int ln = i & 31, ntg = i >> 5, qq = ln & 3;
        b1p[i] = make_float2(b1[8 * ntg + 2 * qq], b1[8 * ntg + 2 * qq + 1]);
    }
    for (int i = tid; i < 256; i += NTHREADS) {            // b2 pairs
        int ln = i & 31, nt = i >> 5, qq = ln & 3;
        b2p[i] = make_float2(b2[8 * nt + 2 * qq], b2[8 * nt + 2 * qq + 1]);
    }
    for (int i = tid; i < 512; i += NTHREADS) {            // W3 rows per frag slot
        int e = i & 1, ln = (i >> 1) & 31, nt = i >> 6, qq = ln & 3;
        int row = 8 * nt + 2 * qq + e;
        w3p[i] = *(const float4*)(W3 + row * 4);
    }
    if (tid == 0) *b3s = *(const float4*)b3;
    __syncthreads();

    const float4 b3r = *b3s;

    for (int tile = blockIdx.x; tile < ntiles; tile += gridDim.x) {
        const int sample = tile * TILE + tid;

        // ---- scalar prologue: x_ls via cofactor inverse / rare fp64 pinv ----
        const float4* xp = (const float4*)x + (size_t)sample * 5;
        const float4 f0 = xp[0], f1 = xp[1], f2 = xp[2], f3 = xp[3], f4 = xp[4];

        const float a00 = f0.x, a01 = f1.x, a02 = f2.x, a03 = f3.x;
        const float a10 = f0.y, a11 = f1.y, a12 = f2.y, a13 = f3.y;
        const float a20 = f0.z, a21 = f1.z, a22 = f2.z, a23 = f3.z;
        const float a30 = f0.w, a31 = f1.w, a32 = f2.w, a33 = f3.w;

        const float s0 = a00 * a11 - a01 * a10;
        const float s1 = a00 * a12 - a02 * a10;
        const float s2 = a00 * a13 - a03 * a10;
        const float s3 = a01 * a12 - a02 * a11;
        const float s4 = a01 * a13 - a03 * a11;
        const float s5 = a02 * a13 - a03 * a12;
        const float c5 = a22 * a33 - a23 * a32;
        const float c4 = a21 * a33 - a23 * a31;
        const float c3 = a21 * a32 - a22 * a31;
        const float c2 = a20 * a33 - a23 * a30;
        const float c1 = a20 * a32 - a22 * a30;
        const float c0 = a20 * a31 - a21 * a30;
        const float det = s0*c5 - s1*c4 + s2*c3 + s3*c2 - s4*c1 + s5*c0;
        const float y0 = f4.x, y1 = f4.y, y2 = f4.z, y3 = f4.w;

        const float F2 =
            a00*a00+a01*a01+a02*a02+a03*a03 + a10*a10+a11*a11+a12*a12+a13*a13 +
            a20*a20+a21*a21+a22*a22+a23*a23 + a30*a30+a31*a31+a32*a32+a33*a33;

        float v0, v1, v2, v3;
        if (fabsf(det) > (3e-5f * F2 * F2 + 1e-5f)) {
            const float iv = 1.0f / det;
            v0 = (( a11*c5 - a12*c4 + a13*c3)*y0 + (-a01*c5 + a02*c4 - a03*c3)*y1 +
                  ( a31*s5 - a32*s4 + a33*s3)*y2 + (-a21*s5 + a22*s4 - a23*s3)*y3) * iv;
            v1 = ((-a10*c5 + a12*c2 - a13*c1)*y0 + ( a00*c5 - a02*c2 + a03*c1)*y1 +
                  (-a30*s5 + a32*s2 - a33*s1)*y2 + ( a20*s5 - a22*s2 + a23*s1)*y3) * iv;
            v2 = (( a10*c4 - a11*c2 + a13*c0)*y0 + (-a00*c4 + a01*c2 - a03*c0)*y1 +
                  ( a30*s4 - a31*s2 + a33*s0)*y2 + (-a20*s4 + a21*s2 - a23*s0)*y3) * iv;
            v3 = ((-a10*c3 + a11*c1 - a12*c0)*y0 + ( a00*c3 - a01*c1 + a02*c0)*y1 +
                  (-a30*s3 + a31*s1 - a32*s0)*y2 + ( a20*s3 - a21*s1 + a22*s0)*y3) * iv;
        } else {
            float hm[16], yv[4], xo[4];
            hm[0]=a00; hm[1]=a01; hm[2]=a02; hm[3]=a03;
            hm[4]=a10; hm[5]=a11; hm[6]=a12; hm[7]=a13;
            hm[8]=a20; hm[9]=a21; hm[10]=a22; hm[11]=a23;
            hm[12]=a30; hm[13]=a31; hm[14]=a32; hm[15]=a33;
            yv[0]=y0; yv[1]=y1; yv[2]=y2; yv[3]=y3;
            pinv_slow(hm, yv, xo);
            v0=xo[0]; v1=xo[1]; v2=xo[2]; v3=xo[3];
        }
        const float xls0 = __saturatef(v0), xls1 = __saturatef(v1);
        const float xls2 = __saturatef(v2), xls3 = __saturatef(v3);

        *(float4*)&xls[lane * 4] = make_float4(xls0, xls1, xls2, xls3);
        __syncwarp();

        // ---- A0 fragments [2 Mtiles][3 Ktiles][4] ----
        const float* xg = x + (size_t)(tile * TILE + wid * 32) * 20;
        uint32_t A0[2][3][4];
#pragma unroll
        for (int m = 0; m < 2; m++) {
            const int r0 = 16 * m + g, r1 = r0 + 8;
#pragma unroll
            for (int kt = 0; kt < 2; kt++) {
                A0[m][kt][0] = f2tf(xg[r0 * 20 + 8 * kt + q]);
                A0[m][kt][1] = f2tf(xg[r1 * 20 + 8 * kt + q]);
                A0[m][kt][2] = f2tf(xg[r0 * 20 + 8 * kt + q + 4]);
                A0[m][kt][3] = f2tf(xg[r1 * 20 + 8 * kt + q + 4]);
            }
            A0[m][2][0] = f2tf(xg[r0 * 20 + 16 + q]);
            A0[m][2][1] = f2tf(xg[r1 * 20 + 16 + q]);
            A0[m][2][2] = f2tf(xls[r0 * 4 + q]);
            A0[m][2][3] = f2tf(xls[r1 * 4 + q]);
        }

        // ---- layers 1+2 chained in 32-col chunks ----
        float C2[2][8][4];
#pragma unroll
        for (int m = 0; m < 2; m++)
#pragma unroll
            for (int nt = 0; nt < 8; nt++)
#pragma unroll
                for (int r = 0; r < 4; r++) C2[m][nt][r] = 0.0f;

#pragma unroll
        for (int nc = 0; nc < 4; nc++) {
            float C1[2][4][4];
#pragma unroll
            for (int m = 0; m < 2; m++)
#pragma unroll
                for (int n = 0; n < 4; n++)
#pragma unroll
                    for (int r = 0; r < 4; r++) C1[m][n][r] = 0.0f;

#pragma unroll
            for (int kt = 0; kt < 3; kt++) {
#pragma unroll
                for (int ntl = 0; ntl < 4; ntl++) {
                    const int ntg = nc * 4 + ntl;
                    uint2 b = *(const uint2*)&w1f[((kt * 16 + ntg) << 6) + (lane << 1)];
                    mma_tf32(C1[0][ntl], A0[0][kt], b.x, b.y);
                    mma_tf32(C1[1][ntl], A0[1][kt], b.x, b.y);
                }
            }

            __syncwarp();   // WAR: prior chunk's A reads done before overwrite
#pragma unroll
            for (int m = 0; m < 2; m++) {
#pragma unroll
                for (int ntl = 0; ntl < 4; ntl++) {
                    const float2 bb = b1p[(nc * 4 + ntl) * 32 + lane];
                    uint32_t t0 = f2tf(fmaxf(C1[m][ntl][0] + bb.x, 0.0f));
                    uint32_t t1 = f2tf(fmaxf(C1[m][ntl][1] + bb.y, 0.0f));
                    uint32_t t2 = f2tf(fmaxf(C1[m][ntl][2] + bb.x, 0.0f));
                    uint32_t t3 = f2tf(fmaxf(C1[m][ntl][3] + bb.y, 0.0f));
                    const int col = 8 * ntl + 2 * q;
                    *(uint2*)&h1[(16 * m + g) * H1_STRIDE + col]     = make_uint2(t0, t1);
                    *(uint2*)&h1[(16 * m + g + 8) * H1_STRIDE + col] = make_uint2(t2, t3);
                }
            }
            __syncwarp();   // RAW: stores visible before A-fragment loads

#pragma unroll
            for (int ktl = 0; ktl < 4; ktl++) {
                uint32_t af[2][4];
#pragma unroll
                for (int m = 0; m < 2; m++) {
                    const int r0 = 16 * m + g, r1 = r0 + 8;
                    af[m][0] = h1[r0 * H1_STRIDE + 8 * ktl + q];
                    af[m][1] = h1[r1 * H1_STRIDE + 8 * ktl + q];
                    af[m][2] = h1[r0 * H1_STRIDE + 8 * ktl + q + 4];
                    af[m][3] = h1[r1 * H1_STRIDE + 8 * ktl + q + 4];
                }
                const int ktg = nc * 4 + ktl;
#pragma unroll
                for (int nt = 0; nt < 8; nt++) {
                    uint2 b = *(const uint2*)&w2f[((ktg * 8 + nt) << 6) + (lane << 1)];
                    mma_tf32(C2[0][nt], af[0], b.x, b.y);
                    mma_tf32(C2[1][nt], af[1], b.x, b.y);
                }
            }
        }

        // ---- layer3 scalar: relu(h2) @ W3, quad-reduced ----
        float p[2][2][4];
#pragma unroll
        for (int m = 0; m < 2; m++)
#pragma unroll
            for (int s = 0; s < 2; s++)
#pragma unroll
                for (int j = 0; j < 4; j++) p[m][s][j] = 0.0f;

#pragma unroll
        for (int nt = 0; nt < 8; nt++) {
            const float2 bb = b2p[nt * 32 + lane];
            const float4 wa = w3p[(nt * 32 + lane) * 2 + 0];
            const float4 wb = w3p[(nt * 32 + lane) * 2 + 1];
#pragma unroll
            for (int m = 0; m < 2; m++) {
                float ha = fmaxf(C2[m][nt][0] + bb.x, 0.0f);
                float hb = fmaxf(C2[m][nt][1] + bb.y, 0.0f);
                p[m][0][0] = fmaf(ha, wa.x, fmaf(hb, wb.x, p[m][0][0]));
                p[m][0][1] = fmaf(ha, wa.y, fmaf(hb, wb.y, p[m][0][1]));
                p[m][0][2] = fmaf(ha, wa.z, fmaf(hb, wb.z, p[m][0][2]));
                p[m][0][3] = fmaf(ha, wa.w, fmaf(hb, wb.w, p[m][0][3]));
                float hc = fmaxf(C2[m][nt][2] + bb.x, 0.0f);
                float hd = fmaxf(C2[m][nt][3] + bb.y, 0.0f);
                p[m][1][0] = fmaf(hc, wa.x, fmaf(hd, wb.x, p[m][1][0]));
                p[m][1][1] = fmaf(hc, wa.y, fmaf(hd, wb.y, p[m][1][1]));
                p[m][1][2] = fmaf(hc, wa.z, fmaf(hd, wb.z, p[m][1][2]));
                p[m][1][3] = fmaf(hc, wa.w, fmaf(hd, wb.w, p[m][1][3]));
            }
        }
#pragma unroll
        for (int m = 0; m < 2; m++)
#pragma unroll
            for (int s = 0; s < 2; s++)
#pragma unroll
                for (int j = 0; j < 4; j++) {
                    p[m][s][j] += __shfl_xor_sync(0xFFFFFFFFu, p[m][s][j], 1);
                    p[m][s][j] += __shfl_xor_sync(0xFFFFFFFFu, p[m][s][j], 2);
                }

        // each quad thread stores one of its 4 rows: q -> (m = q>>1, s = q&1)
        {
            const int msel = q >> 1, ssel = q & 1;
            const int row = 16 * msel + 8 * ssel + g;
            const float4 xv = *(const float4*)&xls[row * 4];
            float4 o;
            o.x = __saturatef(xv.x + p[msel][ssel][0] + b3r.x);
            o.y = __saturatef(xv.y + p[msel][ssel][1] + b3r.y);
            o.z = __saturatef(xv.z + p[msel][ssel][2] + b3r.z);
            o.w = __saturatef(xv.w + p[msel][ssel][3] + b3r.w);
            ((float4*)out)[tile * TILE + wid * 32 + row] = o;
        }
        __syncwarp();   // xls reads done before next iteration overwrites
    }
}

extern "C" void kernel_launch(void* const* d_in, const int* in_sizes, int n_in,
                              void* d_out, int out_size)
{
    const float* x  = (const float*)d_in[0];
    const float* W1 = (const float*)d_in[1];
    const float* b1 = (const float*)d_in[2];
    const float* W2 = (const float*)d_in[3];
    const float* b2 = (const float*)d_in[4];
    const float* W3 = (const float*)d_in[5];
    const float* b3 = (const float*)d_in[6];
    float* out = (float*)d_out;

    const int nsamples = in_sizes[0] / 20;
    const int ntiles = nsamples / TILE;          // 4096
    int grid = 2 * 148;                           // persistent, 2 CTAs/SM
    if (grid > ntiles) grid = ntiles;

    cudaFuncSetAttribute(matrixmlp_hmma,
                         cudaFuncAttributeMaxDynamicSharedMemorySize, SMEM_DYN);
    matrixmlp_hmma<<<grid, NTHREADS, SMEM_DYN>>>(x, W1, b1, W2, b2, W3, b3, out, ntiles);
}

// round 6
// speedup vs baseline: 4.0161x; 2.5141x over previous
#include <cuda_runtime.h>
#include <cuda_bf16.h>
#include <math.h>
#include <stdint.h>

// MatrixMLP R6: scalar 4x4 pinv solve + MLP layers 1-2 on mma.sync tf32
// (m16n8k8), layer 3 scalar fp32. R6 = R5 (tight slow-path gate 6e-6*F2^2,
// 6-sweep Jacobi, 73KB smem -> 3 CTAs/SM) minus the forced minBlocks=3
// (avoids the 170-reg cliff; occupancy comes from smem alone).

#define NTHREADS 128
#define TILE 128
#define RCOND2 2.2737367544323206e-11   // (40*2^-23)^2, JAX pinv fp32 4x4

// ---- smem layout (bytes from dynamic base) ----
#define O_W1F 0            // 3*16*64 u32 tf32 frag-packed  (12288 B)
#define O_W2F 12288        // 16*8*64 u32                   (32768 B)
#define O_B1P 45056        // 512 float2                    (4096 B)
#define O_B2P 49152        // 256 float2                    (2048 B)
#define O_W3R 51200        // 64 float4 raw W3 rows         (1024 B)
#define O_B3  52224        // float4 (+pad)
#define O_XLS 52256        // 4 warps * 32 * float4         (2048 B)
#define O_H1  54304        // 4 warps * 32*40 u32           (20480 B)
#define SMEM_DYN 74784
#define H1_STRIDE 40       // floats per row (64-bit-store conflict-free)

__device__ __forceinline__ uint32_t f2tf(float f) {
    uint32_t r;
    asm("cvt.rna.tf32.f32 %0, %1;" : "=r"(r) : "f"(f));
    return r;
}

__device__ __forceinline__ void mma_tf32(float* c, const uint32_t* a,
                                         uint32_t b0, uint32_t b1) {
    asm volatile(
        "mma.sync.aligned.m16n8k8.row.col.f32.tf32.tf32.f32 "
        "{%0,%1,%2,%3}, {%4,%5,%6,%7}, {%8,%9}, {%0,%1,%2,%3};"
        : "+f"(c[0]), "+f"(c[1]), "+f"(c[2]), "+f"(c[3])
        : "r"(a[0]), "r"(a[1]), "r"(a[2]), "r"(a[3]), "r"(b0), "r"(b1));
}

// ---- rare-path fp64 Jacobi SVD pinv (matches jnp.linalg.pinv truncation) ----
__device__ __noinline__ void pinv_slow(const float* a, const float* yv, float* xout)
{
    double H[4][4], A[4][4], V[4][4];
    for (int r = 0; r < 4; r++)
        for (int c = 0; c < 4; c++) H[r][c] = (double)a[r * 4 + c];
    for (int i = 0; i < 4; i++)
        for (int j = 0; j < 4; j++) {
            double s = 0.0;
            for (int r = 0; r < 4; r++) s += H[r][i] * H[r][j];
            A[i][j] = s; V[i][j] = (i == j) ? 1.0 : 0.0;
        }
    for (int sweep = 0; sweep < 6; sweep++)
        for (int p = 0; p < 3; p++)
            for (int q = p + 1; q < 4; q++) {
                double apq = A[p][q];
                if (fabs(apq) < 1e-300) continue;
                double tau = (A[q][q] - A[p][p]) / (2.0 * apq);
                double t = ((tau >= 0.0) ? 1.0 : -1.0) /
                           (fabs(tau) + sqrt(1.0 + tau * tau));
                double c = 1.0 / sqrt(1.0 + t * t), s = t * c;
                for (int k = 0; k < 4; k++) {
                    double akp = A[k][p], akq = A[k][q];
                    A[k][p] = c * akp - s * akq; A[k][q] = s * akp + c * akq;
                }
                for (int k = 0; k < 4; k++) {
                    double apk = A[p][k], aqk = A[q][k];
                    A[p][k] = c * apk - s * aqk; A[q][k] = s * apk + c * aqk;
                }
                for (int k = 0; k < 4; k++) {
                    double vkp = V[k][p], vkq = V[k][q];
                    V[k][p] = c * vkp - s * vkq; V[k][q] = s * vkp + c * vkq;
                }
            }
    double lam[4], lmax = 0.0;
    for (int i = 0; i < 4; i++) { lam[i] = A[i][i]; if (lam[i] > lmax) lmax = lam[i]; }
    const double thr = RCOND2 * lmax;
    double z[4];
    for (int i = 0; i < 4; i++) {
        double s = 0.0;
        for (int r = 0; r < 4; r++) s += H[r][i] * (double)yv[r];
        z[i] = s;
    }
    double w[4];
    for (int i = 0; i < 4; i++) {
        double s = 0.0;
        for (int k = 0; k < 4; k++) s += V[k][i] * z[k];
        w[i] = (lam[i] > thr) ? (s / lam[i]) : 0.0;
    }
    for (int j = 0; j < 4; j++) {
        double s = 0.0;
        for (int i = 0; i < 4; i++) s += V[j][i] * w[i];
        xout[j] = (float)s;
    }
}

__global__ __launch_bounds__(NTHREADS)
void matrixmlp_hmma(const float* __restrict__ x,
                    const float* __restrict__ W1, const float* __restrict__ b1,
                    const float* __restrict__ W2, const float* __restrict__ b2,
                    const float* __restrict__ W3, const float* __restrict__ b3,
                    float* __restrict__ out, int ntiles)
{
    extern __shared__ char sm[];
    uint32_t* w1f = (uint32_t*)(sm + O_W1F);
    uint32_t* w2f = (uint32_t*)(sm + O_W2F);
    float2*   b1p = (float2*)(sm + O_B1P);
    float2*   b2p = (float2*)(sm + O_B2P);
    float4*   w3r = (float4*)(sm + O_W3R);
    float4*   b3s = (float4*)(sm + O_B3);

    const int tid  = threadIdx.x;
    const int lane = tid & 31;
    const int wid  = tid >> 5;
    const int q    = lane & 3;
    const int g    = lane >> 2;

    float*    xls = (float*)(sm + O_XLS + wid * 512);      // [32][4]
    uint32_t* h1  = (uint32_t*)(sm + O_H1 + wid * (32 * H1_STRIDE * 4));

    // ---- stage fragment-packed weights ----
    for (int i = tid; i < 3072; i += NTHREADS) {           // W1 frags
        int e = i & 1, ln = (i >> 1) & 31, fi = i >> 6;
        int kt = fi >> 4, nt = fi & 15;
        int kk = 8 * kt + (ln & 3) + 4 * e, nn = 8 * nt + (ln >> 2);
        w1f[(fi << 6) + ((ln << 1) | e)] = f2tf(W1[kk * 128 + nn]);
    }
    for (int i = tid; i < 8192; i += NTHREADS) {           // W2 frags
        int e = i & 1, ln = (i >> 1) & 31, fi = i >> 6;
        int kt = fi >> 3, nt = fi & 7;
        int kk = 8 * kt + (ln & 3) + 4 * e, nn = 8 * nt + (ln >> 2);
        w2f[(fi << 6) + ((ln << 1) | e)] = f2tf(W2[kk * 64 + nn]);
    }
    for (int i = tid; i < 512; i += NTHREADS) {            // b1 pairs
        int ln = i & 31, ntg = i >> 5, qq = ln & 3;
        b1p[i] = make_float2(b1[8 * ntg + 2 * qq], b1[8 * ntg + 2 * qq + 1]);
    }
    for (int i = tid; i < 256; i += NTHREADS) {            // b2 pairs
        int ln = i & 31, nt = i >> 5, qq = ln & 3;
        b2p[i] = make_float2(b2[8 * nt + 2 * qq], b2[8 * nt + 2 * qq + 1]);
    }
    for (int i = tid; i < 64; i += NTHREADS)               // W3 raw rows
        w3r[i] = *(const float4*)(W3 + i * 4);
    if (tid == 0) *b3s = *(const float4*)b3;
    __syncthreads();

    const float4 b3r = *b3s;

    for (int tile = blockIdx.x; tile < ntiles; tile += gridDim.x) {
        const int sample = tile * TILE + tid;

        // ---- scalar prologue: x_ls via cofactor inverse / rare fp64 pinv ----
        const float4* xp = (const float4*)x + (size_t)sample * 5;
        const float4 f0 = xp[0], f1 = xp[1], f2 = xp[2], f3 = xp[3], f4 = xp[4];

        const float a00 = f0.x, a01 = f1.x, a02 = f2.x, a03 = f3.x;
        const float a10 = f0.y, a11 = f1.y, a12 = f2.y, a13 = f3.y;
        const float a20 = f0.z, a21 = f1.z, a22 = f2.z, a23 = f3.z;
        const float a30 = f0.w, a31 = f1.w, a32 = f2.w, a33 = f3.w;

        const float s0 = a00 * a11 - a01 * a10;
        const float s1 = a00 * a12 - a02 * a10;
        const float s2 = a00 * a13 - a03 * a10;
        const float s3 = a01 * a12 - a02 * a11;
        const float s4 = a01 * a13 - a03 * a11;
        const float s5 = a02 * a13 - a03 * a12;
        const float c5 = a22 * a33 - a23 * a32;
        const float c4 = a21 * a33 - a23 * a31;
        const float c3 = a21 * a32 - a22 * a31;
        const float c2 = a20 * a33 - a23 * a30;
        const float c1 = a20 * a32 - a22 * a30;
        const float c0 = a20 * a31 - a21 * a30;
        const float det = s0*c5 - s1*c4 + s2*c3 + s3*c2 - s4*c1 + s5*c0;
        const float y0 = f4.x, y1 = f4.y, y2 = f4.z, y3 = f4.w;

        const float F2 =
            a00*a00+a01*a01+a02*a02+a03*a03 + a10*a10+a11*a11+a12*a12+a13*a13 +
            a20*a20+a21*a21+a22*a22+a23*a23 + a30*a30+a31*a31+a32*a32+a33*a33;

        float v0, v1, v2, v3;
        // Reference truncation requires |det| < rcond*F^4/8 = 6e-7*F2^2.
        // Gate at 10x that; everything above is safely exact-inverse territory.
        if (fabsf(det) > 6e-6f * F2 * F2) {
            const float iv = 1.0f / det;
            v0 = (( a11*c5 - a12*c4 + a13*c3)*y0 + (-a01*c5 + a02*c4 - a03*c3)*y1 +
                  ( a31*s5 - a32*s4 + a33*s3)*y2 + (-a21*s5 + a22*s4 - a23*s3)*y3) * iv;
            v1 = ((-a10*c5 + a12*c2 - a13*c1)*y0 + ( a00*c5 - a02*c2 + a03*c1)*y1 +
                  (-a30*s5 + a32*s2 - a33*s1)*y2 + ( a20*s5 - a22*s2 + a23*s1)*y3) * iv;
            v2 = (( a10*c4 - a11*c2 + a13*c0)*y0 + (-a00*c4 + a01*c2 - a03*c0)*y1 +
                  ( a30*s4 - a31*s2 + a33*s0)*y2 + (-a20*s4 + a21*s2 - a23*s0)*y3) * iv;
            v3 = ((-a10*c3 + a11*c1 - a12*c0)*y0 + ( a00*c3 - a01*c1 + a02*c0)*y1 +
                  (-a30*s3 + a31*s1 - a32*s0)*y2 + ( a20*s3 - a21*s1 + a22*s0)*y3) * iv;
        } else {
            float hm[16], yv[4], xo[4];
            hm[0]=a00; hm[1]=a01; hm[2]=a02; hm[3]=a03;
            hm[4]=a10; hm[5]=a11; hm[6]=a12; hm[7]=a13;
            hm[8]=a20; hm[9]=a21; hm[10]=a22; hm[11]=a23;
            hm[12]=a30; hm[13]=a31; hm[14]=a32; hm[15]=a33;
            yv[0]=y0; yv[1]=y1; yv[2]=y2; yv[3]=y3;
            pinv_slow(hm, yv, xo);
            v0=xo[0]; v1=xo[1]; v2=xo[2]; v3=xo[3];
        }
        const float xls0 = __saturatef(v0), xls1 = __saturatef(v1);
        const float xls2 = __saturatef(v2), xls3 = __saturatef(v3);

        *(float4*)&xls[lane * 4] = make_float4(xls0, xls1, xls2, xls3);
        __syncwarp();

        // ---- A0 fragments [2 Mtiles][3 Ktiles][4] ----
        const float* xg = x + (size_t)(tile * TILE + wid * 32) * 20;
        uint32_t A0[2][3][4];
#pragma unroll
        for (int m = 0; m < 2; m++) {
            const int r0 = 16 * m + g, r1 = r0 + 8;
#pragma unroll
            for (int kt = 0; kt < 2; kt++) {
                A0[m][kt][0] = f2tf(xg[r0 * 20 + 8 * kt + q]);
                A0[m][kt][1] = f2tf(xg[r1 * 20 + 8 * kt + q]);
                A0[m][kt][2] = f2tf(xg[r0 * 20 + 8 * kt + q + 4]);
                A0[m][kt][3] = f2tf(xg[r1 * 20 + 8 * kt + q + 4]);
            }
            A0[m][2][0] = f2tf(xg[r0 * 20 + 16 + q]);
            A0[m][2][1] = f2tf(xg[r1 * 20 + 16 + q]);
            A0[m][2][2] = f2tf(xls[r0 * 4 + q]);
            A0[m][2][3] = f2tf(xls[r1 * 4 + q]);
        }

        // ---- layers 1+2 chained in 32-col chunks ----
        float C2[2][8][4];
#pragma unroll
        for (int m = 0; m < 2; m++)
#pragma unroll
            for (int nt = 0; nt < 8; nt++)
#pragma unroll
                for (int r = 0; r < 4; r++) C2[m][nt][r] = 0.0f;

#pragma unroll
        for (int nc = 0; nc < 4; nc++) {
            float C1[2][4][4];
#pragma unroll
            for (int m = 0; m < 2; m++)
#pragma unroll
                for (int n = 0; n < 4; n++)
#pragma unroll
                    for (int r = 0; r < 4; r++) C1[m][n][r] = 0.0f;

#pragma unroll
            for (int kt = 0; kt < 3; kt++) {
#pragma unroll
                for (int ntl = 0; ntl < 4; ntl++) {
                    const int ntg = nc * 4 + ntl;
                    uint2 b = *(const uint2*)&w1f[((kt * 16 + ntg) << 6) + (lane << 1)];
                    mma_tf32(C1[0][ntl], A0[0][kt], b.x, b.y);
                    mma_tf32(C1[1][ntl], A0[1][kt], b.x, b.y);
                }
            }

            __syncwarp();   // WAR: prior chunk's A reads done before overwrite
#pragma unroll
            for (int m = 0; m < 2; m++) {
#pragma unroll
                for (int ntl = 0; ntl < 4; ntl++) {
                    const float2 bb = b1p[(nc * 4 + ntl) * 32 + lane];
                    uint32_t t0 = f2tf(fmaxf(C1[m][ntl][0] + bb.x, 0.0f));
                    uint32_t t1 = f2tf(fmaxf(C1[m][ntl][1] + bb.y, 0.0f));
                    uint32_t t2 = f2tf(fmaxf(C1[m][ntl][2] + bb.x, 0.0f));
                    uint32_t t3 = f2tf(fmaxf(C1[m][ntl][3] + bb.y, 0.0f));
                    const int col = 8 * ntl + 2 * q;
                    *(uint2*)&h1[(16 * m + g) * H1_STRIDE + col]     = make_uint2(t0, t1);
                    *(uint2*)&h1[(16 * m + g + 8) * H1_STRIDE + col] = make_uint2(t2, t3);
                }
            }
            __syncwarp();   // RAW: stores visible before A-fragment loads

#pragma unroll
            for (int ktl = 0; ktl < 4; ktl++) {
                uint32_t af[2][4];
#pragma unroll
                for (int m = 0; m < 2; m++) {
                    const int r0 = 16 * m + g, r1 = r0 + 8;
                    af[m][0] = h1[r0 * H1_STRIDE + 8 * ktl + q];
                    af[m][1] = h1[r1 * H1_STRIDE + 8 * ktl + q];
                    af[m][2] = h1[r0 * H1_STRIDE + 8 * ktl + q + 4];
                    af[m][3] = h1[r1 * H1_STRIDE + 8 * ktl + q + 4];
                }
                const int ktg = nc * 4 + ktl;
#pragma unroll
                for (int nt = 0; nt < 8; nt++) {
                    uint2 b = *(const uint2*)&w2f[((ktg * 8 + nt) << 6) + (lane << 1)];
                    mma_tf32(C2[0][nt], af[0], b.x, b.y);
                    mma_tf32(C2[1][nt], af[1], b.x, b.y);
                }
            }
        }

        // ---- layer3 scalar: relu(h2) @ W3, quad-reduced ----
        float p[2][2][4];
#pragma unroll
        for (int m = 0; m < 2; m++)
#pragma unroll
            for (int s = 0; s < 2; s++)
#pragma unroll
                for (int j = 0; j < 4; j++) p[m][s][j] = 0.0f;

#pragma unroll
        for (int nt = 0; nt < 8; nt++) {
            const float2 bb = b2p[nt * 32 + lane];
            const int row = 8 * nt + 2 * q;
            const float4 wa = w3r[row];
            const float4 wb = w3r[row + 1];
#pragma unroll
            for (int m = 0; m < 2; m++) {
                float ha = fmaxf(C2[m][nt][0] + bb.x, 0.0f);
                float hb = fmaxf(C2[m][nt][1] + bb.y, 0.0f);
                p[m][0][0] = fmaf(ha, wa.x, fmaf(hb, wb.x, p[m][0][0]));
                p[m][0][1] = fmaf(ha, wa.y, fmaf(hb, wb.y, p[m][0][1]));
                p[m][0][2] = fmaf(ha, wa.z, fmaf(hb, wb.z, p[m][0][2]));
                p[m][0][3] = fmaf(ha, wa.w, fmaf(hb, wb.w, p[m][0][3]));
                float hc = fmaxf(C2[m][nt][2] + bb.x, 0.0f);
                float hd = fmaxf(C2[m][nt][3] + bb.y, 0.0f);
                p[m][1][0] = fmaf(hc, wa.x, fmaf(hd, wb.x, p[m][1][0]));
                p[m][1][1] = fmaf(hc, wa.y, fmaf(hd, wb.y, p[m][1][1]));
                p[m][1][2] = fmaf(hc, wa.z, fmaf(hd, wb.z, p[m][1][2]));
                p[m][1][3] = fmaf(hc, wa.w, fmaf(hd, wb.w, p[m][1][3]));
            }
        }
#pragma unroll
        for (int m = 0; m < 2; m++)
#pragma unroll
            for (int s = 0; s < 2; s++)
#pragma unroll
                for (int j = 0; j < 4; j++) {
                    p[m][s][j] += __shfl_xor_sync(0xFFFFFFFFu, p[m][s][j], 1);
                    p[m][s][j] += __shfl_xor_sync(0xFFFFFFFFu, p[m][s][j], 2);
                }

        // each quad thread stores one of its 4 rows: q -> (m = q>>1, s = q&1)
        {
            const int msel = q >> 1, ssel = q & 1;
            const int row = 16 * msel + 8 * ssel + g;
            const float4 xv = *(const float4*)&xls[row * 4];
            float4 o;
            o.x = __saturatef(xv.x + p[msel][ssel][0] + b3r.x);
            o.y = __saturatef(xv.y + p[msel][ssel][1] + b3r.y);
            o.z = __saturatef(xv.z + p[msel][ssel][2] + b3r.z);
            o.w = __saturatef(xv.w + p[msel][ssel][3] + b3r.w);
            ((float4*)out)[tile * TILE + wid * 32 + row] = o;
        }
        __syncwarp();   // xls reads done before next iteration overwrites
    }
}

extern "C" void kernel_launch(void* const* d_in, const int* in_sizes, int n_in,
                              void* d_out, int out_size)
{
    const float* x  = (const float*)d_in[0];
    const float* W1 = (const float*)d_in[1];
    const float* b1 = (const float*)d_in[2];
    const float* W2 = (const float*)d_in[3];
    const float* b2 = (const float*)d_in[4];
    const float* W3 = (const float*)d_in[5];
    const float* b3 = (const float*)d_in[6];
    float* out = (float*)d_out;

    const int nsamples = in_sizes[0] / 20;
    const int ntiles = nsamples / TILE;          // 4096
    int grid = 3 * 148;                           // persistent; 3 CTAs/SM via smem
    if (grid > ntiles) grid = ntiles;

    cudaFuncSetAttribute(matrixmlp_hmma,
                         cudaFuncAttributeMaxDynamicSharedMemorySize, SMEM_DYN);
    matrixmlp_hmma<<<grid, NTHREADS, SMEM_DYN>>>(x, W1, b1, W2, b2, W3, b3, out, ntiles);
}

// round 8
// speedup vs baseline: 5.6394x; 1.4042x over previous
#include <cuda_runtime.h>
#include <cuda_bf16.h>
#include <math.h>
#include <stdint.h>

// MatrixMLP R8: scalar 4x4 pinv solve + layer1 tf32 mma (m16n8k8) chained
// IN REGISTERS into layer2 bf16 mma (m16n8k16) via C-frag -> A-frag packing.
// No smem h1 round trip, no mainloop syncwarps. Layer3 scalar fp32.
// R8 = R7 device code with R6's proven hardcoded launch (no occupancy API).

#define NTHREADS 128
#define TILE 128
#define RCOND2 2.2737367544323206e-11   // (40*2^-23)^2, JAX pinv fp32 4x4

// ---- smem layout (bytes from dynamic base) ----
#define O_W1F 0            // 48 frags * 64 u32 tf32        (12288 B)
#define O_W2F 12288        // 64 frags * 64 u32 bf16x2      (16384 B)
#define O_B1P 28672        // 512 float2                    (4096 B)
#define O_B2P 32768        // 256 float2                    (2048 B)
#define O_W3R 34816        // 64 float4 raw W3 rows         (1024 B)
#define O_B3  35840        // float4 (+pad)
#define O_XLS 35872        // 4 warps * 32 * float4         (2048 B)
#define SMEM_DYN 37920

__device__ __forceinline__ uint32_t f2tf(float f) {
    uint32_t r;
    asm("cvt.rna.tf32.f32 %0, %1;" : "=r"(r) : "f"(f));
    return r;
}
// pack (lo, hi) floats into bf16x2 (lo in bits [0:16))
__device__ __forceinline__ uint32_t packbf(float lo, float hi) {
    uint32_t r;
    asm("cvt.rn.bf16x2.f32 %0, %1, %2;" : "=r"(r) : "f"(hi), "f"(lo));
    return r;
}

__device__ __forceinline__ void mma_tf32(float* c, const uint32_t* a,
                                         uint32_t b0, uint32_t b1) {
    asm volatile(
        "mma.sync.aligned.m16n8k8.row.col.f32.tf32.tf32.f32 "
        "{%0,%1,%2,%3}, {%4,%5,%6,%7}, {%8,%9}, {%0,%1,%2,%3};"
        : "+f"(c[0]), "+f"(c[1]), "+f"(c[2]), "+f"(c[3])
        : "r"(a[0]), "r"(a[1]), "r"(a[2]), "r"(a[3]), "r"(b0), "r"(b1));
}
__device__ __forceinline__ void mma_bf16(float* c, const uint32_t* a,
                                         uint32_t b0, uint32_t b1) {
    asm volatile(
        "mma.sync.aligned.m16n8k16.row.col.f32.bf16.bf16.f32 "
        "{%0,%1,%2,%3}, {%4,%5,%6,%7}, {%8,%9}, {%0,%1,%2,%3};"
        : "+f"(c[0]), "+f"(c[1]), "+f"(c[2]), "+f"(c[3])
        : "r"(a[0]), "r"(a[1]), "r"(a[2]), "r"(a[3]), "r"(b0), "r"(b1));
}

// ---- rare-path fp64 Jacobi SVD pinv (matches jnp.linalg.pinv truncation) ----
__device__ __noinline__ void pinv_slow(const float* a, const float* yv, float* xout)
{
    double H[4][4], A[4][4], V[4][4];
    for (int r = 0; r < 4; r++)
        for (int c = 0; c < 4; c++) H[r][c] = (double)a[r * 4 + c];
    for (int i = 0; i < 4; i++)
        for (int j = 0; j < 4; j++) {
            double s = 0.0;
            for (int r = 0; r < 4; r++) s += H[r][i] * H[r][j];
            A[i][j] = s; V[i][j] = (i == j) ? 1.0 : 0.0;
        }
    for (int sweep = 0; sweep < 6; sweep++)
        for (int p = 0; p < 3; p++)
            for (int q = p + 1; q < 4; q++) {
                double apq = A[p][q];
                if (fabs(apq) < 1e-300) continue;
                double tau = (A[q][q] - A[p][p]) / (2.0 * apq);
                double t = ((tau >= 0.0) ? 1.0 : -1.0) /
                           (fabs(tau) + sqrt(1.0 + tau * tau));
                double c = 1.0 / sqrt(1.0 + t * t), s = t * c;
                for (int k = 0; k < 4; k++) {
                    double akp = A[k][p], akq = A[k][q];
                    A[k][p] = c * akp - s * akq; A[k][q] = s * akp + c * akq;
                }
                for (int k = 0; k < 4; k++) {
                    double apk = A[p][k], aqk = A[q][k];
                    A[p][k] = c * apk - s * aqk; A[q][k] = s * apk + c * aqk;
                }
                for (int k = 0; k < 4; k++) {
                    double vkp = V[k][p], vkq = V[k][q];
                    V[k][p] = c * vkp - s * vkq; V[k][q] = s * vkp + c * vkq;
                }
            }
    double lam[4], lmax = 0.0;
    for (int i = 0; i < 4; i++) { lam[i] = A[i][i]; if (lam[i] > lmax) lmax = lam[i]; }
    const double thr = RCOND2 * lmax;
    double z[4];
    for (int i = 0; i < 4; i++) {
        double s = 0.0;
        for (int r = 0; r < 4; r++) s += H[r][i] * (double)yv[r];
        z[i] = s;
    }
    double w[4];
    for (int i = 0; i < 4; i++) {
        double s = 0.0;
        for (int k = 0; k < 4; k++) s += V[k][i] * z[k];
        w[i] = (lam[i] > thr) ? (s / lam[i]) : 0.0;
    }
    for (int j = 0; j < 4; j++) {
        double s = 0.0;
        for (int i = 0; i < 4; i++) s += V[j][i] * w[i];
        xout[j] = (float)s;
    }
}

__global__ __launch_bounds__(NTHREADS)
void matrixmlp_hmma(const float* __restrict__ x,
                    const float* __restrict__ W1, const float* __restrict__ b1,
                    const float* __restrict__ W2, const float* __restrict__ b2,
                    const float* __restrict__ W3, const float* __restrict__ b3,
                    float* __restrict__ out, int ntiles)
{
    extern __shared__ char sm[];
    uint32_t* w1f = (uint32_t*)(sm + O_W1F);
    uint32_t* w2f = (uint32_t*)(sm + O_W2F);
    float2*   b1p = (float2*)(sm + O_B1P);
    float2*   b2p = (float2*)(sm + O_B2P);
    float4*   w3r = (float4*)(sm + O_W3R);
    float4*   b3s = (float4*)(sm + O_B3);

    const int tid  = threadIdx.x;
    const int lane = tid & 31;
    const int wid  = tid >> 5;
    const int q    = lane & 3;
    const int g    = lane >> 2;

    float* xls = (float*)(sm + O_XLS + wid * 512);         // [32][4]

    // ---- stage weights ----
    for (int i = tid; i < 3072; i += NTHREADS) {           // W1 tf32 k8 frags
        int e = i & 1, ln = (i >> 1) & 31, fi = i >> 6;
        int kt = fi >> 4, nt = fi & 15;
        int kk = 8 * kt + (ln & 3) + 4 * e, nn = 8 * nt + (ln >> 2);
        w1f[(fi << 6) + ((ln << 1) | e)] = f2tf(W1[kk * 128 + nn]);
    }
    for (int i = tid; i < 4096; i += NTHREADS) {           // W2 bf16 k16 frags
        int e = i & 1, ln = (i >> 1) & 31, fi = i >> 6;
        int kt = fi >> 3, nt = fi & 7;
        int k0 = 16 * kt + 2 * (ln & 3) + 8 * e, nn = 8 * nt + (ln >> 2);
        w2f[(fi << 6) + ((ln << 1) | e)] =
            packbf(W2[k0 * 64 + nn], W2[(k0 + 1) * 64 + nn]);
    }
    for (int i = tid; i < 512; i += NTHREADS) {            // b1 pairs
        int ln = i & 31, ntg = i >> 5, qq = ln & 3;
        b1p[i] = make_float2(b1[8 * ntg + 2 * qq], b1[8 * ntg + 2 * qq + 1]);
    }
    for (int i = tid; i < 256; i += NTHREADS) {            // b2 pairs
        int ln = i & 31, nt = i >> 5, qq = ln & 3;
        b2p[i] = make_float2(b2[8 * nt + 2 * qq], b2[8 * nt + 2 * qq + 1]);
    }
    for (int i = tid; i < 64; i += NTHREADS)               // W3 raw rows
        w3r[i] = *(const float4*)(W3 + i * 4);
    if (tid == 0) *b3s = *(const float4*)b3;
    __syncthreads();

    const float4 b3r = *b3s;

    for (int tile = blockIdx.x; tile < ntiles; tile += gridDim.x) {
        const int sample = tile * TILE + tid;

        // ---- scalar prologue: x_ls via cofactor inverse / rare fp64 pinv ----
        const float4* xp = (const float4*)x + (size_t)sample * 5;
        const float4 f0 = xp[0], f1 = xp[1], f2 = xp[2], f3 = xp[3], f4 = xp[4];

        const float a00 = f0.x, a01 = f1.x, a02 = f2.x, a03 = f3.x;
        const float a10 = f0.y, a11 = f1.y, a12 = f2.y, a13 = f3.y;
        const float a20 = f0.z, a21 = f1.z, a22 = f2.z, a23 = f3.z;
        const float a30 = f0.w, a31 = f1.w, a32 = f2.w, a33 = f3.w;

        const float s0 = a00 * a11 - a01 * a10;
        const float s1 = a00 * a12 - a02 * a10;
        const float s2 = a00 * a13 - a03 * a10;
        const float s3 = a01 * a12 - a02 * a11;
        const float s4 = a01 * a13 - a03 * a11;
        const float s5 = a02 * a13 - a03 * a12;
        const float c5 = a22 * a33 - a23 * a32;
        const float c4 = a21 * a33 - a23 * a31;
        const float c3 = a21 * a32 - a22 * a31;
        const float c2 = a20 * a33 - a23 * a30;
        const float c1 = a20 * a32 - a22 * a30;
        const float c0 = a20 * a31 - a21 * a30;
        const float det = s0*c5 - s1*c4 + s2*c3 + s3*c2 - s4*c1 + s5*c0;
        const float y0 = f4.x, y1 = f4.y, y2 = f4.z, y3 = f4.w;

        const float F2 =
            a00*a00+a01*a01+a02*a02+a03*a03 + a10*a10+a11*a11+a12*a12+a13*a13 +
            a20*a20+a21*a21+a22*a22+a23*a23 + a30*a30+a31*a31+a32*a32+a33*a33;

        float v0, v1, v2, v3;
        if (fabsf(det) > 6e-6f * F2 * F2) {
            const float iv = 1.0f / det;
            v0 = (( a11*c5 - a12*c4 + a13*c3)*y0 + (-a01*c5 + a02*c4 - a03*c3)*y1 +
                  ( a31*s5 - a32*s4 + a33*s3)*y2 + (-a21*s5 + a22*s4 - a23*s3)*y3) * iv;
            v1 = ((-a10*c5 + a12*c2 - a13*c1)*y0 + ( a00*c5 - a02*c2 + a03*c1)*y1 +
                  (-a30*s5 + a32*s2 - a33*s1)*y2 + ( a20*s5 - a22*s2 + a23*s1)*y3) * iv;
            v2 = (( a10*c4 - a11*c2 + a13*c0)*y0 + (-a00*c4 + a01*c2 - a03*c0)*y1 +
                  ( a30*s4 - a31*s2 + a33*s0)*y2 + (-a20*s4 + a21*s2 - a23*s0)*y3) * iv;
            v3 = ((-a10*c3 + a11*c1 - a12*c0)*y0 + ( a00*c3 - a01*c1 + a02*c0)*y1 +
                  (-a30*s3 + a31*s1 - a32*s0)*y2 + ( a20*s3 - a21*s1 + a22*s0)*y3) * iv;
        } else {
            float hm[16], yv[4], xo[4];
            hm[0]=a00; hm[1]=a01; hm[2]=a02; hm[3]=a03;
            hm[4]=a10; hm[5]=a11; hm[6]=a12; hm[7]=a13;
            hm[8]=a20; hm[9]=a21; hm[10]=a22; hm[11]=a23;
            hm[12]=a30; hm[13]=a31; hm[14]=a32; hm[15]=a33;
            yv[0]=y0; yv[1]=y1; yv[2]=y2; yv[3]=y3;
            pinv_slow(hm, yv, xo);
            v0=xo[0]; v1=xo[1]; v2=xo[2]; v3=xo[3];
        }
        const float xls0 = __saturatef(v0), xls1 = __saturatef(v1);
        const float xls2 = __saturatef(v2), xls3 = __saturatef(v3);

        *(float4*)&xls[lane * 4] = make_float4(xls0, xls1, xls2, xls3);
        __syncwarp();

        // ---- A0 tf32 fragments [2 Mtiles][3 Ktiles][4] ----
        const float* xg = x + (size_t)(tile * TILE + wid * 32) * 20;
        uint32_t A0[2][3][4];
#pragma unroll
        for (int m = 0; m < 2; m++) {
            const int r0 = 16 * m + g, r1 = r0 + 8;
#pragma unroll
            for (int kt = 0; kt < 2; kt++) {
                A0[m][kt][0] = f2tf(xg[r0 * 20 + 8 * kt + q]);
                A0[m][kt][1] = f2tf(xg[r1 * 20 + 8 * kt + q]);
                A0[m][kt][2] = f2tf(xg[r0 * 20 + 8 * kt + q + 4]);
                A0[m][kt][3] = f2tf(xg[r1 * 20 + 8 * kt + q + 4]);
            }
            A0[m][2][0] = f2tf(xg[r0 * 20 + 16 + q]);
            A0[m][2][1] = f2tf(xg[r1 * 20 + 16 + q]);
            A0[m][2][2] = f2tf(xls[r0 * 4 + q]);
            A0[m][2][3] = f2tf(xls[r1 * 4 + q]);
        }
        __syncwarp();

        // ---- layers 1+2: tf32 MMA -> in-register bf16 A-frag -> bf16 MMA ----
        float C2[2][8][4];
#pragma unroll
        for (int m = 0; m < 2; m++)
#pragma unroll
            for (int nt = 0; nt < 8; nt++)
#pragma unroll
                for (int r = 0; r < 4; r++) C2[m][nt][r] = 0.0f;

#pragma unroll 1
        for (int c = 0; c < 8; c++) {
            float C1[2][2][4];
#pragma unroll
            for (int m = 0; m < 2; m++)
#pragma unroll
                for (int t = 0; t < 2; t++)
#pragma unroll
                    for (int r = 0; r < 4; r++) C1[m][t][r] = 0.0f;

#pragma unroll
            for (int kt = 0; kt < 3; kt++) {
#pragma unroll
                for (int t = 0; t < 2; t++) {
                    uint2 b = *(const uint2*)
                        &w1f[((kt * 16 + 2 * c + t) << 6) + (lane << 1)];
                    mma_tf32(C1[0][t], A0[0][kt], b.x, b.y);
                    mma_tf32(C1[1][t], A0[1][kt], b.x, b.y);
                }
            }

            // relu + bias, pack C-frag pairs -> m16n8k16 bf16 A-frag
            const float2 bb0 = b1p[(2 * c) * 32 + lane];
            const float2 bb1 = b1p[(2 * c + 1) * 32 + lane];
            uint32_t af[2][4];
#pragma unroll
            for (int m = 0; m < 2; m++) {
                af[m][0] = packbf(fmaxf(C1[m][0][0] + bb0.x, 0.0f),
                                  fmaxf(C1[m][0][1] + bb0.y, 0.0f));
                af[m][1] = packbf(fmaxf(C1[m][0][2] + bb0.x, 0.0f),
                                  fmaxf(C1[m][0][3] + bb0.y, 0.0f));
                af[m][2] = packbf(fmaxf(C1[m][1][0] + bb1.x, 0.0f),
                                  fmaxf(C1[m][1][1] + bb1.y, 0.0f));
                af[m][3] = packbf(fmaxf(C1[m][1][2] + bb1.x, 0.0f),
                                  fmaxf(C1[m][1][3] + bb1.y, 0.0f));
            }

#pragma unroll
            for (int nt = 0; nt < 8; nt++) {
                uint2 b = *(const uint2*)&w2f[((c * 8 + nt) << 6) + (lane << 1)];
                mma_bf16(C2[0][nt], af[0], b.x, b.y);
                mma_bf16(C2[1][nt], af[1], b.x, b.y);
            }
        }

        // ---- layer3 scalar: relu(h2) @ W3, quad-reduced ----
        float p[2][2][4];
#pragma unroll
        for (int m = 0; m < 2; m++)
#pragma unroll
            for (int s = 0; s < 2; s++)
#pragma unroll
                for (int j = 0; j < 4; j++) p[m][s][j] = 0.0f;

#pragma unroll
        for (int nt = 0; nt < 8; nt++) {
            const float2 bb = b2p[nt * 32 + lane];
            const int row = 8 * nt + 2 * q;
            const float4 wa = w3r[row];
            const float4 wb = w3r[row + 1];
#pragma unroll
            for (int m = 0; m < 2; m++) {
                float ha = fmaxf(C2[m][nt][0] + bb.x, 0.0f);
                float hb = fmaxf(C2[m][nt][1] + bb.y, 0.0f);
                p[m][0][0] = fmaf(ha, wa.x, fmaf(hb, wb.x, p[m][0][0]));
                p[m][0][1] = fmaf(ha, wa.y, fmaf(hb, wb.y, p[m][0][1]));
                p[m][0][2] = fmaf(ha, wa.z, fmaf(hb, wb.z, p[m][0][2]));
                p[m][0][3] = fmaf(ha, wa.w, fmaf(hb, wb.w, p[m][0][3]));
                float hc = fmaxf(C2[m][nt][2] + bb.x, 0.0f);
                float hd = fmaxf(C2[m][nt][3] + bb.y, 0.0f);
                p[m][1][0] = fmaf(hc, wa.x, fmaf(hd, wb.x, p[m][1][0]));
                p[m][1][1] = fmaf(hc, wa.y, fmaf(hd, wb.y, p[m][1][1]));
                p[m][1][2] = fmaf(hc, wa.z, fmaf(hd, wb.z, p[m][1][2]));
                p[m][1][3] = fmaf(hc, wa.w, fmaf(hd, wb.w, p[m][1][3]));
            }
        }
#pragma unroll
        for (int m = 0; m < 2; m++)
#pragma unroll
            for (int s = 0; s < 2; s++)
#pragma unroll
                for (int j = 0; j < 4; j++) {
                    p[m][s][j] += __shfl_xor_sync(0xFFFFFFFFu, p[m][s][j], 1);
                    p[m][s][j] += __shfl_xor_sync(0xFFFFFFFFu, p[m][s][j], 2);
                }

        // each quad thread stores one of its 4 rows: q -> (m = q>>1, s = q&1)
        {
            const int msel = q >> 1, ssel = q & 1;
            const int row = 16 * msel + 8 * ssel + g;
            const float4 xv = *(const float4*)&xls[row * 4];
            float4 o;
            o.x = __saturatef(xv.x + p[msel][ssel][0] + b3r.x);
            o.y = __saturatef(xv.y + p[msel][ssel][1] + b3r.y);
            o.z = __saturatef(xv.z + p[msel][ssel][2] + b3r.z);
            o.w = __saturatef(xv.w + p[msel][ssel][3] + b3r.w);
            ((float4*)out)[tile * TILE + wid * 32 + row] = o;
        }
        __syncwarp();   // xls reads done before next iteration overwrites
    }
}

extern "C" void kernel_launch(void* const* d_in, const int* in_sizes, int n_in,
                              void* d_out, int out_size)
{
    const float* x  = (const float*)d_in[0];
    const float* W1 = (const float*)d_in[1];
    const float* b1 = (const float*)d_in[2];
    const float* W2 = (const float*)d_in[3];
    const float* b2 = (const float*)d_in[4];
    const float* W3 = (const float*)d_in[5];
    const float* b3 = (const float*)d_in[6];
    float* out = (float*)d_out;

    const int nsamples = in_sizes[0] / 20;
    const int ntiles = nsamples / 128;           // 4096
    int grid = 3 * 148;                          // persistent; reg-limited 3 CTAs/SM
    if (grid > ntiles) grid = ntiles;

    cudaFuncSetAttribute(matrixmlp_hmma,
                         cudaFuncAttributeMaxDynamicSharedMemorySize, SMEM_DYN);
    matrixmlp_hmma<<<grid, NTHREADS, SMEM_DYN>>>(x, W1, b1, W2, b2, W3, b3, out, ntiles);
}